// round 16
// baseline (speedup 1.0000x reference)
#include <cuda_runtime.h>
#include <math.h>

#define NN 20000
#define FF 8
#define PP 12
#define OO 32
#define EE 320000
#define FP 96           // F*P floats per node row
#define SLOTS 96        // max in-degree slots (Poisson(16); guarded)
#define NSM 148
#define NBPS 4
#define NBLK (NSM * NBPS)            // 592 blocks, all co-resident
#define NTHR 256
#define WPB (NTHR / 32)              // 8 warps per block
#define SOWP 36                      // padded out_w row stride (bank-safe, 16B-aligned)
#define FULL 0xffffffffu

// ---- scratch (static device globals; no allocation allowed) ----
__device__ int      g_cnt[NN];            // in-degree (atomic counters)
__device__ int      g_col[NN * SLOTS];    // slotted adjacency: srcs per dst
__device__ float    g_cwz[FF * OO];       // fused Wz @ Lz^T
__device__ float    g_cwh[FF * OO];       // fused Wh @ Lh^T
__device__ float    g_cbz[OO];
__device__ float    g_cbh[OO];
__device__ float    g_probs[PP];
__device__ unsigned g_node_ctr;           // P3 dynamic work counter (reset in P0)
__device__ unsigned g_bar[2];             // monotonic barrier counters (never reset)

// Monotonic grid barrier: all NBLK blocks co-resident (4/SM via launch bounds).
__device__ __forceinline__ void grid_barrier(int id) {
    __syncthreads();
    if (threadIdx.x == 0) {
        __threadfence();                                      // release
        unsigned arrived = atomicAdd(&g_bar[id], 1u) + 1u;
        unsigned target  = ((arrived + NBLK - 1u) / NBLK) * NBLK;
        while (*(volatile unsigned*)&g_bar[id] < target) { }
        __threadfence();                                      // acquire
    }
    __syncthreads();
}

// Packed fp32x2 helpers (Blackwell FFMA2 — only reachable via PTX)
__device__ __forceinline__ unsigned long long pack2(float lo, float hi) {
    unsigned long long r;
    asm("mov.b64 %0, {%1, %2};" : "=l"(r) : "f"(lo), "f"(hi));
    return r;
}
__device__ __forceinline__ void unpack2(unsigned long long v, float& lo, float& hi) {
    asm("mov.b64 {%0, %1}, %2;" : "=f"(lo), "=f"(hi) : "l"(v));
}
__device__ __forceinline__ unsigned long long ffma2(
        unsigned long long a, unsigned long long b, unsigned long long c) {
    unsigned long long d;
    asm("fma.rn.f32x2 %0, %1, %2, %3;" : "=l"(d) : "l"(a), "l"(b), "l"(c));
    return d;
}
// HW tanh (MUFU.TANH), rel err ~1e-5 — far inside the 1e-3 budget
__device__ __forceinline__ float htanh(float x) {
    float r;
    asm("tanh.approx.f32 %0, %1;" : "=f"(r) : "f"(x));
    return r;
}

// Per-node prologue state, loaded one pipeline stage ahead.
// dinv values are computed from cnt via MUFU.RSQ (no dinv array, no extra phase).
struct Prolog {
    int    deg;     // clamped degree
    float  di;      // (deg+1)^-1/2 for the node
    int    ci;      // lane's slot col (clamped-valid, masked later)
    float  wv;      // rsqrt(cnt[ci]+1) (masked later)
    float4 xv;      // self row chunk (lane < 24)
};

__device__ __forceinline__ Prolog load_prolog(
        int node, int lane, const float* __restrict__ x) {
    Prolog p;
    int   deg = __ldg(&g_cnt[node]);
    int   raw = __ldg(&g_col[node * SLOTS + lane]);   // always in-bounds (SLOTS>=32)
    int   cl  = raw < 0 ? 0 : (raw >= NN ? NN - 1 : raw);
    int   cc  = __ldg(&g_cnt[cl]);
    p.xv = (lane < 24) ? __ldg((const float4*)(x + (size_t)node * FP) + lane)
                       : make_float4(0.f, 0.f, 0.f, 0.f);
    p.di = rsqrtf((float)(deg + 1));
    float wv = rsqrtf((float)(cc + 1));
    if (deg > SLOTS) deg = SLOTS;
    p.deg = deg;
    p.ci  = (lane < deg) ? cl : 0;
    p.wv  = (lane < deg) ? wv : 0.f;
    return p;
}

__global__ void __launch_bounds__(NTHR, NBPS) fused_kernel(
        const float* __restrict__ x,
        const int*   __restrict__ ei,
        const float* __restrict__ Wz,  const float* __restrict__ bz,
        const float* __restrict__ Wh,  const float* __restrict__ bh,
        const float* __restrict__ lzw, const float* __restrict__ lzb,
        const float* __restrict__ lhw, const float* __restrict__ lhb,
        const float* __restrict__ att,
        const float* __restrict__ out_w, const float* __restrict__ out_b,
        float* __restrict__ out) {
    const int t    = threadIdx.x;
    const int lane = t & 31;
    const int warp = t >> 5;                 // 0..7
    const int gid  = blockIdx.x * NTHR + t;
    const int T    = NBLK * NTHR;

    __shared__ __align__(16) float buf[WPB][2][FP];  // GRU staging, per warp, 2 nodes
    __shared__ __align__(16) float hrb[WPB][2][OO];  // hr staging for readout
    __shared__ __align__(16) float sow[PP * SOWP];   // padded out_w
    __shared__ float sob[PP];                        // staged out_b
    __shared__ float sp2[PP];                        // 0.5 * softmax(att)

    // ---------------- P0: zero counters + fold weights (blocks 0..2) -------
    for (int j = gid; j < NN; j += T) g_cnt[j] = 0;

    if (blockIdx.x == 0) {                   // W'_z[f][o] = sum_k Wz[f][k]*lzw[o][k]
        int f = t >> 5, o = t & 31;
        float s = 0.f;
        #pragma unroll
        for (int k = 0; k < 32; ++k) s = fmaf(Wz[f * 32 + k], lzw[o * 64 + k], s);
        g_cwz[t] = s;
    } else if (blockIdx.x == 1) {            // W'_h
        int f = t >> 5, o = t & 31;
        float s = 0.f;
        #pragma unroll
        for (int k = 0; k < 32; ++k) s = fmaf(Wh[f * 32 + k], lhw[o * 64 + k], s);
        g_cwh[t] = s;
    } else if (blockIdx.x == 2) {
        if (t < 32) {                        // b'_z
            float s = lzb[t];
            #pragma unroll
            for (int k = 0; k < 32; ++k) s = fmaf(bz[k], lzw[t * 64 + k], s);
            g_cbz[t] = s;
        } else if (t < 64) {                 // b'_h
            int o = t - 32;
            float s = lhb[o];
            #pragma unroll
            for (int k = 0; k < 32; ++k) s = fmaf(bh[k], lhw[o * 64 + k], s);
            g_cbh[o] = s;
        } else if (t == 64) {                // softmax over 12 logits
            float m = att[0];
            for (int p = 1; p < PP; ++p) m = fmaxf(m, att[p]);
            float e[PP], sum = 0.f;
            for (int p = 0; p < PP; ++p) { e[p] = __expf(att[p] - m); sum += e[p]; }
            float inv = 1.f / sum;
            for (int p = 0; p < PP; ++p) g_probs[p] = e[p] * inv;
        }
        if (t == 65) g_node_ctr = 0;         // reset P3 work counter
    }
    grid_barrier(0);

    // ---------------- P1: single-pass slotted scatter -----------------------
    {
        const int4* s4p = (const int4*)ei;
        const int4* d4p = (const int4*)(ei + EE);
        for (int q = gid; q < EE / 4; q += T) {
            int4 s4 = s4p[q];
            int4 d4 = d4p[q];
            int p0 = atomicAdd(&g_cnt[d4.x], 1);
            int p1 = atomicAdd(&g_cnt[d4.y], 1);
            int p2 = atomicAdd(&g_cnt[d4.z], 1);
            int p3 = atomicAdd(&g_cnt[d4.w], 1);
            if (p0 < SLOTS) g_col[d4.x * SLOTS + p0] = s4.x;
            if (p1 < SLOTS) g_col[d4.y * SLOTS + p1] = s4.y;
            if (p2 < SLOTS) g_col[d4.z * SLOTS + p2] = s4.z;
            if (p3 < SLOTS) g_col[d4.w * SLOTS + p3] = s4.w;
        }
    }
    grid_barrier(1);

    // ---------------- P3: software-pipelined gather + GRU + readout --------
    {
        if (t < PP) sp2[t] = 0.5f * g_probs[t];   // fold sigmoid's 0.5
        if (t < PP) sob[t] = out_b[t];
        for (int j = t; j < PP * OO; j += NTHR) {
            int p = j >> 5, k = j & 31;
            sow[p * SOWP + k] = out_w[j];
        }
        __syncthreads();

        float wzr[FF], whr[FF];
        #pragma unroll
        for (int f = 0; f < FF; ++f) {
            wzr[f] = g_cwz[f * OO + lane];
            whr[f] = g_cwh[f * OO + lane];
        }
        const float bz_ = g_cbz[lane];
        const float bh_ = g_cbh[lane];

        int base;
        if (lane == 0) base = (int)atomicAdd(&g_node_ctr, 2u);
        base = __shfl_sync(FULL, base, 0);
        Prolog pA, pB;
        if (base < NN) {                     // NN even -> base+1 valid too
            pA = load_prolog(base, lane, x);
            pB = load_prolog(base + 1, lane, x);
        }

        while (base < NN) {
            // -------- gather both nodes (prologue + self row resolved) -----
            #pragma unroll
            for (int i = 0; i < 2; ++i) {
                const Prolog& pr = (i == 0) ? pA : pB;
                const int node = base + i;
                float4 acc = make_float4(0.f, 0.f, 0.f, 0.f);

                int ci = pr.ci; float wv = pr.wv;
                int deg4 = (pr.deg + 3) & ~3;
                for (int b = 0; b < deg4; b += 32) {
                    if (b) {                                  // rare: deg > 32
                        int raw = __ldg(&g_col[node * SLOTS + b + lane]);
                        int cl = raw < 0 ? 0 : (raw >= NN ? NN - 1 : raw);
                        float w2 = rsqrtf((float)(__ldg(&g_cnt[cl]) + 1));
                        ci = (b + lane < pr.deg) ? cl : 0;
                        wv = (b + lane < pr.deg) ? w2 : 0.f;
                    }
                    int nb = deg4 - b; if (nb > 32) nb = 32;
                    for (int k = 0; k < nb; k += 4) {
                        int   s0 = __shfl_sync(FULL, ci, k);
                        int   s1 = __shfl_sync(FULL, ci, k + 1);
                        int   s2 = __shfl_sync(FULL, ci, k + 2);
                        int   s3 = __shfl_sync(FULL, ci, k + 3);
                        float w0 = __shfl_sync(FULL, wv, k);
                        float w1 = __shfl_sync(FULL, wv, k + 1);
                        float w2 = __shfl_sync(FULL, wv, k + 2);
                        float w3 = __shfl_sync(FULL, wv, k + 3);
                        if (lane < 24) {
                            float4 v0 = __ldg((const float4*)(x + (size_t)s0 * FP) + lane);
                            float4 v1 = __ldg((const float4*)(x + (size_t)s1 * FP) + lane);
                            float4 v2 = __ldg((const float4*)(x + (size_t)s2 * FP) + lane);
                            float4 v3 = __ldg((const float4*)(x + (size_t)s3 * FP) + lane);
                            acc.x = fmaf(w0, v0.x, acc.x); acc.y = fmaf(w0, v0.y, acc.y);
                            acc.z = fmaf(w0, v0.z, acc.z); acc.w = fmaf(w0, v0.w, acc.w);
                            acc.x = fmaf(w1, v1.x, acc.x); acc.y = fmaf(w1, v1.y, acc.y);
                            acc.z = fmaf(w1, v1.z, acc.z); acc.w = fmaf(w1, v1.w, acc.w);
                            acc.x = fmaf(w2, v2.x, acc.x); acc.y = fmaf(w2, v2.y, acc.y);
                            acc.z = fmaf(w2, v2.z, acc.z); acc.w = fmaf(w2, v2.w, acc.w);
                            acc.x = fmaf(w3, v3.x, acc.x); acc.y = fmaf(w3, v3.y, acc.y);
                            acc.z = fmaf(w3, v3.z, acc.z); acc.w = fmaf(w3, v3.w, acc.w);
                        }
                    }
                }
                if (lane < 24) {              // agg = di*(acc + di*x_self)
                    float di = pr.di;
                    acc.x = di * fmaf(di, pr.xv.x, acc.x);
                    acc.y = di * fmaf(di, pr.xv.y, acc.y);
                    acc.z = di * fmaf(di, pr.xv.z, acc.z);
                    acc.w = di * fmaf(di, pr.xv.w, acc.w);
                    ((float4*)buf[warp][i])[lane] = acc;
                }
            }
            const int obase = base;
            __syncwarp();

            // -------- pop + prefetch NEXT pair BEFORE the GRU compute ------
            if (lane == 0) base = (int)atomicAdd(&g_node_ctr, 2u);
            base = __shfl_sync(FULL, base, 0);
            if (base < NN) {
                pA = load_prolog(base, lane, x);       // hidden by GRU below
                pB = load_prolog(base + 1, lane, x);
            }

            // -------- GRU (3 passes over period-quads, low reg) + readout --
            #pragma unroll
            for (int i = 0; i < 2; ++i) {
                const float* bw = buf[warp][i];
                float hacc = 0.f;
                #pragma unroll
                for (int g = 0; g < 3; ++g) {       // periods 4g..4g+3
                    unsigned long long zp0 = pack2(bz_, bz_), zp1 = zp0;
                    unsigned long long hp0 = pack2(bh_, bh_), hp1 = hp0;
                    #pragma unroll
                    for (int f = 0; f < FF; ++f) {
                        ulonglong2 v = *(const ulonglong2*)&bw[f * PP + 4 * g];
                        unsigned long long wz2 = pack2(wzr[f], wzr[f]);
                        unsigned long long wh2 = pack2(whr[f], whr[f]);
                        zp0 = ffma2(v.x, wz2, zp0);
                        hp0 = ffma2(v.x, wh2, hp0);
                        zp1 = ffma2(v.y, wz2, zp1);
                        hp1 = ffma2(v.y, wh2, hp1);
                    }
                    // probs*(1-Z)*tanh(h), Z = 0.5 + 0.5*tanh(z/2)
                    float z0, z1, z2, z3, h0, h1, h2, h3;
                    unpack2(zp0, z0, z1); unpack2(zp1, z2, z3);
                    unpack2(hp0, h0, h1); unpack2(hp1, h2, h3);
                    hacc = fmaf(sp2[4*g],   (1.f - htanh(0.5f*z0)) * htanh(h0), hacc);
                    hacc = fmaf(sp2[4*g+1], (1.f - htanh(0.5f*z1)) * htanh(h1), hacc);
                    hacc = fmaf(sp2[4*g+2], (1.f - htanh(0.5f*z2)) * htanh(h2), hacc);
                    hacc = fmaf(sp2[4*g+3], (1.f - htanh(0.5f*z3)) * htanh(h3), hacc);
                }
                hrb[warp][i][lane] = fmaxf(hacc, 0.f);   // relu, stage for readout
            }
            __syncwarp();

            // -------- readout via smem (no shfl chains): lanes 0..11 -------
            #pragma unroll
            for (int i = 0; i < 2; ++i) {
                if (lane < PP) {
                    const float* hv = hrb[warp][i];
                    const float* wrow = sow + lane * SOWP;
                    float v = sob[lane];
                    #pragma unroll
                    for (int k = 0; k < OO; k += 4) {
                        float4 h4 = *(const float4*)&hv[k];     // broadcast
                        float4 w4 = *(const float4*)&wrow[k];   // bank-padded
                        v = fmaf(h4.x, w4.x, v);
                        v = fmaf(h4.y, w4.y, v);
                        v = fmaf(h4.z, w4.z, v);
                        v = fmaf(h4.w, w4.w, v);
                    }
                    out[(obase + i) * PP + lane] = v;
                }
            }
            __syncwarp();                    // smem reads done before next pair
        }
    }
}

// ---------------------------------------------------------------------------
extern "C" void kernel_launch(void* const* d_in, const int* in_sizes, int n_in,
                              void* d_out, int out_size) {
    const float* x    = (const float*)d_in[0];
    const int*   ei   = (const int*)  d_in[1];
    const float* Wz   = (const float*)d_in[2];
    const float* bz   = (const float*)d_in[3];
    // d_in[4], d_in[5]: Wr, br — dead code (H == 0 kills the reset gate)
    const float* Wh   = (const float*)d_in[6];
    const float* bh   = (const float*)d_in[7];
    const float* lzw  = (const float*)d_in[8];
    const float* lzb  = (const float*)d_in[9];
    // d_in[10], d_in[11]: lr_w, lr_b — unused
    const float* lhw  = (const float*)d_in[12];
    const float* lhb  = (const float*)d_in[13];
    const float* att  = (const float*)d_in[14];
    const float* outw = (const float*)d_in[15];
    const float* outb = (const float*)d_in[16];
    float* out = (float*)d_out;

    fused_kernel<<<NBLK, NTHR>>>(x, ei, Wz, bz, Wh, bh, lzw, lzb, lhw, lhb,
                                 att, outw, outb, out);
}

// round 17
// speedup vs baseline: 1.0576x; 1.0576x over previous
#include <cuda_runtime.h>
#include <math.h>

#define NN 20000
#define FF 8
#define PP 12
#define OO 32
#define EE 320000
#define FP 96           // F*P floats per node row
#define SLOTS 96        // max in-degree slots (Poisson(16); guarded)
#define NSM 148
#define NBPS 3
#define NBLK (NSM * NBPS)            // 444 blocks, all co-resident
#define NTHR 256
#define WPB (NTHR / 32)              // 8 warps per block
#define SOWP 36                      // padded out_w row stride (bank-safe, 16B-aligned)
#define FULL 0xffffffffu

typedef unsigned long long ull;

// ---- scratch (static device globals; no allocation allowed) ----
__device__ int      g_cnt[NN];            // in-degree (atomic counters)
__device__ int      g_col[NN * SLOTS];    // slotted adjacency: srcs per dst
__device__ float    g_cwz[FF * OO];       // fused Wz @ Lz^T
__device__ float    g_cwh[FF * OO];       // fused Wh @ Lh^T
__device__ float    g_cbz[OO];
__device__ float    g_cbh[OO];
__device__ float    g_probs[PP];
__device__ unsigned g_node_ctr;           // P3 dynamic work counter (reset in P0)
__device__ unsigned g_bar[2];             // monotonic barrier counters (never reset)

// Monotonic grid barrier: all NBLK blocks co-resident (3/SM via launch bounds).
__device__ __forceinline__ void grid_barrier(int id) {
    __syncthreads();
    if (threadIdx.x == 0) {
        __threadfence();                                      // release
        unsigned arrived = atomicAdd(&g_bar[id], 1u) + 1u;
        unsigned target  = ((arrived + NBLK - 1u) / NBLK) * NBLK;
        while (*(volatile unsigned*)&g_bar[id] < target) { }
        __threadfence();                                      // acquire
    }
    __syncthreads();
}

// Packed fp32x2 helpers (Blackwell FFMA2 — only reachable via PTX)
__device__ __forceinline__ ull pack2(float lo, float hi) {
    ull r;
    asm("mov.b64 %0, {%1, %2};" : "=l"(r) : "f"(lo), "f"(hi));
    return r;
}
__device__ __forceinline__ void unpack2(ull v, float& lo, float& hi) {
    asm("mov.b64 {%0, %1}, %2;" : "=f"(lo), "=f"(hi) : "l"(v));
}
__device__ __forceinline__ ull ffma2(ull a, ull b, ull c) {
    ull d;
    asm("fma.rn.f32x2 %0, %1, %2, %3;" : "=l"(d) : "l"(a), "l"(b), "l"(c));
    return d;
}
__device__ __forceinline__ ull fmul2(ull a, ull b) {
    ull d;
    asm("mul.rn.f32x2 %0, %1, %2;" : "=l"(d) : "l"(a), "l"(b));
    return d;
}
// HW tanh (MUFU.TANH), rel err ~1e-5 — far inside the 1e-3 budget
__device__ __forceinline__ float htanh(float x) {
    float r;
    asm("tanh.approx.f32 %0, %1;" : "=f"(r) : "f"(x));
    return r;
}

// slot word: low 32 = col index, high 32 = weight bits
__device__ __forceinline__ ull slot_pack(int ci, float wv) {
    return ((ull)__float_as_uint(wv) << 32) | (unsigned)ci;
}
__device__ __forceinline__ int  slot_col(ull sv) { return (int)(unsigned)sv; }
__device__ __forceinline__ float slot_w(ull sv)  { return __uint_as_float((unsigned)(sv >> 32)); }

// Per-node prologue: resolves deg/di/self-row into regs and the lane's
// (col, weight) slot into shared memory (read back later via LDS broadcast).
struct Prolog {
    int    deg;     // clamped degree
    float  di;      // (deg+1)^-1/2 for the node
    float4 xv;      // self row chunk (lane < 24)
};

__device__ __forceinline__ Prolog load_prolog(
        int node, int lane, const float* __restrict__ x, ull* slotdst) {
    Prolog p;
    int   deg = __ldg(&g_cnt[node]);
    int   raw = __ldg(&g_col[node * SLOTS + lane]);   // always in-bounds (SLOTS>=32)
    int   cl  = raw < 0 ? 0 : (raw >= NN ? NN - 1 : raw);
    int   cc  = __ldg(&g_cnt[cl]);
    p.xv = (lane < 24) ? __ldg((const float4*)(x + (size_t)node * FP) + lane)
                       : make_float4(0.f, 0.f, 0.f, 0.f);
    p.di = rsqrtf((float)(deg + 1));
    float wv = rsqrtf((float)(cc + 1));
    if (deg > SLOTS) deg = SLOTS;
    p.deg = deg;
    slotdst[lane] = slot_pack((lane < deg) ? cl : 0, (lane < deg) ? wv : 0.f);
    return p;
}

__global__ void __launch_bounds__(NTHR, NBPS) fused_kernel(
        const float* __restrict__ x,
        const int*   __restrict__ ei,
        const float* __restrict__ Wz,  const float* __restrict__ bz,
        const float* __restrict__ Wh,  const float* __restrict__ bh,
        const float* __restrict__ lzw, const float* __restrict__ lzb,
        const float* __restrict__ lhw, const float* __restrict__ lhb,
        const float* __restrict__ att,
        const float* __restrict__ out_w, const float* __restrict__ out_b,
        float* __restrict__ out) {
    const int t    = threadIdx.x;
    const int lane = t & 31;
    const int warp = t >> 5;                 // 0..7
    const int gid  = blockIdx.x * NTHR + t;
    const int T    = NBLK * NTHR;

    __shared__ __align__(16) float buf[WPB][2][FP];  // GRU staging, per warp, 2 nodes
    __shared__ __align__(16) ull  slb[WPB][2][32];   // slot (col,w) staging
    __shared__ __align__(16) float hrb[WPB][2][OO];  // hr staging for readout
    __shared__ __align__(16) float sow[PP * SOWP];   // padded out_w
    __shared__ float sob[PP];                        // staged out_b
    __shared__ float sp2[PP];                        // 0.5 * softmax(att)

    // ---------------- P0: zero counters + fold weights (blocks 0..2) -------
    for (int j = gid; j < NN; j += T) g_cnt[j] = 0;

    if (blockIdx.x == 0) {                   // W'_z[f][o] = sum_k Wz[f][k]*lzw[o][k]
        int f = t >> 5, o = t & 31;
        float s = 0.f;
        #pragma unroll
        for (int k = 0; k < 32; ++k) s = fmaf(Wz[f * 32 + k], lzw[o * 64 + k], s);
        g_cwz[t] = s;
    } else if (blockIdx.x == 1) {            // W'_h
        int f = t >> 5, o = t & 31;
        float s = 0.f;
        #pragma unroll
        for (int k = 0; k < 32; ++k) s = fmaf(Wh[f * 32 + k], lhw[o * 64 + k], s);
        g_cwh[t] = s;
    } else if (blockIdx.x == 2) {
        if (t < 32) {                        // b'_z
            float s = lzb[t];
            #pragma unroll
            for (int k = 0; k < 32; ++k) s = fmaf(bz[k], lzw[t * 64 + k], s);
            g_cbz[t] = s;
        } else if (t < 64) {                 // b'_h
            int o = t - 32;
            float s = lhb[o];
            #pragma unroll
            for (int k = 0; k < 32; ++k) s = fmaf(bh[k], lhw[o * 64 + k], s);
            g_cbh[o] = s;
        } else if (t == 64) {                // softmax over 12 logits
            float m = att[0];
            for (int p = 1; p < PP; ++p) m = fmaxf(m, att[p]);
            float e[PP], sum = 0.f;
            for (int p = 0; p < PP; ++p) { e[p] = __expf(att[p] - m); sum += e[p]; }
            float inv = 1.f / sum;
            for (int p = 0; p < PP; ++p) g_probs[p] = e[p] * inv;
        }
        if (t == 65) g_node_ctr = 0;         // reset P3 work counter
    }
    grid_barrier(0);

    // ---------------- P1: single-pass slotted scatter -----------------------
    {
        const int4* s4p = (const int4*)ei;
        const int4* d4p = (const int4*)(ei + EE);
        for (int q = gid; q < EE / 4; q += T) {
            int4 s4 = s4p[q];
            int4 d4 = d4p[q];
            int p0 = atomicAdd(&g_cnt[d4.x], 1);
            int p1 = atomicAdd(&g_cnt[d4.y], 1);
            int p2 = atomicAdd(&g_cnt[d4.z], 1);
            int p3 = atomicAdd(&g_cnt[d4.w], 1);
            if (p0 < SLOTS) g_col[d4.x * SLOTS + p0] = s4.x;
            if (p1 < SLOTS) g_col[d4.y * SLOTS + p1] = s4.y;
            if (p2 < SLOTS) g_col[d4.z * SLOTS + p2] = s4.z;
            if (p3 < SLOTS) g_col[d4.w * SLOTS + p3] = s4.w;
        }
    }
    grid_barrier(1);

    // ---------------- P3: software-pipelined gather + GRU + readout --------
    {
        if (t < PP) sp2[t] = 0.5f * g_probs[t];   // fold sigmoid's 0.5
        if (t < PP) sob[t] = out_b[t];
        for (int j = t; j < PP * OO; j += NTHR) {
            int p = j >> 5, k = j & 31;
            sow[p * SOWP + k] = out_w[j];
        }
        __syncthreads();

        float wzr[FF], whr[FF];
        #pragma unroll
        for (int f = 0; f < FF; ++f) {
            wzr[f] = g_cwz[f * OO + lane];
            whr[f] = g_cwh[f * OO + lane];
        }
        const float bz_ = g_cbz[lane];
        const float bh_ = g_cbh[lane];

        int base;
        if (lane == 0) base = (int)atomicAdd(&g_node_ctr, 2u);
        base = __shfl_sync(FULL, base, 0);
        Prolog pA, pB;
        if (base < NN) {                     // NN even -> base+1 valid too
            pA = load_prolog(base, lane, x, slb[warp][0]);
            pB = load_prolog(base + 1, lane, x, slb[warp][1]);
        }
        __syncwarp();

        while (base < NN) {
            // -------- gather both nodes (slots via LDS broadcast) ----------
            #pragma unroll
            for (int i = 0; i < 2; ++i) {
                const Prolog& pr = (i == 0) ? pA : pB;
                const int node = base + i;
                const ull* sl = slb[warp][i];
                ull a01 = 0, a23 = 0;                 // packed f32x2 accumulators

                int deg4 = (pr.deg + 3) & ~3;
                for (int b = 0; b < deg4; b += 32) {
                    if (b) {                          // rare: deg > 32, restage
                        int raw = __ldg(&g_col[node * SLOTS + b + lane]);
                        int cl = raw < 0 ? 0 : (raw >= NN ? NN - 1 : raw);
                        float w2 = rsqrtf((float)(__ldg(&g_cnt[cl]) + 1));
                        slb[warp][i][lane] = slot_pack(
                            (b + lane < pr.deg) ? cl : 0,
                            (b + lane < pr.deg) ? w2 : 0.f);
                        __syncwarp();
                    }
                    int nb = deg4 - b; if (nb > 32) nb = 32;
                    for (int k = 0; k < nb; k += 4) {
                        ull sv0 = sl[k];              // LDS.64 broadcast
                        ull sv1 = sl[k + 1];
                        ull sv2 = sl[k + 2];
                        ull sv3 = sl[k + 3];
                        if (lane < 24) {
                            ulonglong2 v0 = __ldg((const ulonglong2*)(x + (size_t)slot_col(sv0) * FP) + lane);
                            ulonglong2 v1 = __ldg((const ulonglong2*)(x + (size_t)slot_col(sv1) * FP) + lane);
                            ulonglong2 v2 = __ldg((const ulonglong2*)(x + (size_t)slot_col(sv2) * FP) + lane);
                            ulonglong2 v3 = __ldg((const ulonglong2*)(x + (size_t)slot_col(sv3) * FP) + lane);
                            ull w0 = pack2(slot_w(sv0), slot_w(sv0));
                            ull w1 = pack2(slot_w(sv1), slot_w(sv1));
                            ull w2 = pack2(slot_w(sv2), slot_w(sv2));
                            ull w3 = pack2(slot_w(sv3), slot_w(sv3));
                            a01 = ffma2(v0.x, w0, a01); a23 = ffma2(v0.y, w0, a23);
                            a01 = ffma2(v1.x, w1, a01); a23 = ffma2(v1.y, w1, a23);
                            a01 = ffma2(v2.x, w2, a01); a23 = ffma2(v2.y, w2, a23);
                            a01 = ffma2(v3.x, w3, a01); a23 = ffma2(v3.y, w3, a23);
                        }
                    }
                }
                if (lane < 24) {              // agg = di*(acc + di*x_self)
                    ull di2  = pack2(pr.di, pr.di);
                    ull xv01 = pack2(pr.xv.x, pr.xv.y);
                    ull xv23 = pack2(pr.xv.z, pr.xv.w);
                    ull r01 = fmul2(ffma2(xv01, di2, a01), di2);
                    ull r23 = fmul2(ffma2(xv23, di2, a23), di2);
                    ulonglong2 st; st.x = r01; st.y = r23;
                    ((ulonglong2*)buf[warp][i])[lane] = st;
                }
            }
            const int obase = base;
            __syncwarp();

            // -------- pop + prefetch NEXT pair BEFORE the GRU compute ------
            if (lane == 0) base = (int)atomicAdd(&g_node_ctr, 2u);
            base = __shfl_sync(FULL, base, 0);
            if (base < NN) {
                pA = load_prolog(base, lane, x, slb[warp][0]);  // hidden by GRU
                pB = load_prolog(base + 1, lane, x, slb[warp][1]);
            }

            // -------- GRU + readout for both nodes (pure compute) ----------
            #pragma unroll
            for (int i = 0; i < 2; ++i) {
                const float* bw = buf[warp][i];
                ull zp[PP / 2], hp[PP / 2];
                {
                    ull bz2 = pack2(bz_, bz_);
                    ull bh2 = pack2(bh_, bh_);
                    #pragma unroll
                    for (int q = 0; q < PP / 2; ++q) { zp[q] = bz2; hp[q] = bh2; }
                }
                #pragma unroll
                for (int f = 0; f < FF; ++f) {
                    ull wz2 = pack2(wzr[f], wzr[f]);
                    ull wh2 = pack2(whr[f], whr[f]);
                    #pragma unroll
                    for (int j = 0; j < PP / 4; ++j) {    // LDS.128: two f32x2 pairs
                        ulonglong2 v = *(const ulonglong2*)&bw[f * PP + 4 * j];
                        zp[2*j]   = ffma2(v.x, wz2, zp[2*j]);
                        hp[2*j]   = ffma2(v.x, wh2, hp[2*j]);
                        zp[2*j+1] = ffma2(v.y, wz2, zp[2*j+1]);
                        hp[2*j+1] = ffma2(v.y, wh2, hp[2*j+1]);
                    }
                }
                // probs*(1-Z)*tanh(h), Z = 0.5 + 0.5*tanh(z/2)
                float hacc = 0.f;
                #pragma unroll
                for (int q = 0; q < PP / 2; ++q) {
                    float z0, z1, h0, h1;
                    unpack2(zp[q], z0, z1);
                    unpack2(hp[q], h0, h1);
                    float tz0 = htanh(0.5f * z0);
                    float tz1 = htanh(0.5f * z1);
                    float th0 = htanh(h0);
                    float th1 = htanh(h1);
                    hacc = fmaf(sp2[2 * q],     (1.f - tz0) * th0, hacc);
                    hacc = fmaf(sp2[2 * q + 1], (1.f - tz1) * th1, hacc);
                }
                hrb[warp][i][lane] = fmaxf(hacc, 0.f);   // relu, stage for readout
            }
            __syncwarp();

            // -------- readout via smem (no shfl chains): lanes 0..11 -------
            #pragma unroll
            for (int i = 0; i < 2; ++i) {
                if (lane < PP) {
                    const float* hv = hrb[warp][i];
                    const float* wrow = sow + lane * SOWP;
                    float v = sob[lane];
                    #pragma unroll
                    for (int k = 0; k < OO; k += 4) {
                        float4 h4 = *(const float4*)&hv[k];     // broadcast
                        float4 w4 = *(const float4*)&wrow[k];   // bank-padded
                        v = fmaf(h4.x, w4.x, v);
                        v = fmaf(h4.y, w4.y, v);
                        v = fmaf(h4.z, w4.z, v);
                        v = fmaf(h4.w, w4.w, v);
                    }
                    out[(obase + i) * PP + lane] = v;
                }
            }
            __syncwarp();                    // smem reads done before next pair
        }
    }
}

// ---------------------------------------------------------------------------
extern "C" void kernel_launch(void* const* d_in, const int* in_sizes, int n_in,
                              void* d_out, int out_size) {
    const float* x    = (const float*)d_in[0];
    const int*   ei   = (const int*)  d_in[1];
    const float* Wz   = (const float*)d_in[2];
    const float* bz   = (const float*)d_in[3];
    // d_in[4], d_in[5]: Wr, br — dead code (H == 0 kills the reset gate)
    const float* Wh   = (const float*)d_in[6];
    const float* bh   = (const float*)d_in[7];
    const float* lzw  = (const float*)d_in[8];
    const float* lzb  = (const float*)d_in[9];
    // d_in[10], d_in[11]: lr_w, lr_b — unused
    const float* lhw  = (const float*)d_in[12];
    const float* lhb  = (const float*)d_in[13];
    const float* att  = (const float*)d_in[14];
    const float* outw = (const float*)d_in[15];
    const float* outb = (const float*)d_in[16];
    float* out = (float*)d_out;

    fused_kernel<<<NBLK, NTHR>>>(x, ei, Wz, bz, Wh, bh, lzw, lzb, lhw, lhb,
                                 att, outw, outb, out);
}